// round 1
// baseline (speedup 1.0000x reference)
#include <cuda_runtime.h>
#include <cstdint>
#include <cstddef>

// ---------------------------------------------------------------------------
// AddInterpolant: xt, dt_xt from a 4-layer MLP + JVP wrt the t input column.
//
//   z = [x0 | x1 | t]                         (B, 513)
//   pre1 = z@W1 + b1;  h1 = relu(pre1);  dpre1 = W1[512,:];  dh1 = mask*dpre1
//   pre2 = h1@W2 + b2; h2 = relu;        dpre2 = dh1@W2;     dh2 = mask*dpre2
//   pre3 = h2@W3 + b3; h3 = relu;        dpre3 = dh2@W3;     dh3 = mask*dpre3
//   fnn  = h3@W4 + b4;                   dtfnn = dh3@W4
//   xt    = (1-t)x0 + t x1 + t(1-t) fnn
//   dt_xt = x1 - x0 + (1-2t) fnn + t(1-t) dtfnn
//
// Round 1: fp32 SIMT GEMMs using packed fma.rn.f32x2 (FFMA2) inner loops.
// ---------------------------------------------------------------------------

constexpr int BATCH = 65536;
constexpr int SDIM  = 256;
constexpr int HID   = 1024;

constexpr int BM = 128;
constexpr int BN = 64;
constexpr int BK = 16;
constexpr int BMP = BM + 8;   // padded row length for transposed A tiles
constexpr int BNP = BN + 4;   // padded row length for W tiles
constexpr int NTHREADS = 256;

// Ping-pong scratch for activations + tangents (1 GB total; static device mem
// is the sanctioned scratch mechanism — no allocations in kernel_launch).
__device__ float g_hA [(size_t)BATCH * HID];
__device__ float g_dhA[(size_t)BATCH * HID];
__device__ float g_hB [(size_t)BATCH * HID];
__device__ float g_dhB[(size_t)BATCH * HID];

// ---------------------------------------------------------------------------
// f32x2 packed helpers (Blackwell packed fp32 pipe; only reachable via PTX)
// ---------------------------------------------------------------------------
__device__ __forceinline__ unsigned long long bcast2(float v) {
    unsigned long long r;
    asm("mov.b64 %0, {%1, %1};" : "=l"(r) : "f"(v));
    return r;
}
__device__ __forceinline__ void fma2(unsigned long long& d,
                                     unsigned long long a,
                                     unsigned long long b) {
    asm("fma.rn.f32x2 %0, %1, %2, %0;" : "+l"(d) : "l"(a), "l"(b));
}
__device__ __forceinline__ void unpack2(unsigned long long v, float& lo, float& hi) {
    asm("mov.b64 {%0, %1}, %2;" : "=f"(lo), "=f"(hi) : "l"(v));
}

// ---------------------------------------------------------------------------
// Tile loaders
// ---------------------------------------------------------------------------
// Load a BM x BK tile of row-major src (leading dim lda) into transposed
// shared tile As[BK][BMP]. float4 gmem loads, scalar transposed STS.
__device__ __forceinline__ void load_a_tile(float (*As)[BMP],
                                            const float* __restrict__ src,
                                            int row0, int k0, int lda, int tid) {
#pragma unroll
    for (int it = 0; it < (BM * BK / 4) / NTHREADS; ++it) {
        int idx = it * NTHREADS + tid;      // 0 .. 511
        int m = idx >> 2;                   // 0 .. 127
        int c = idx & 3;                    // quad within row
        const float4 v = *reinterpret_cast<const float4*>(
            src + (size_t)(row0 + m) * lda + (k0 + c * 4));
        As[c * 4 + 0][m] = v.x;
        As[c * 4 + 1][m] = v.y;
        As[c * 4 + 2][m] = v.z;
        As[c * 4 + 3][m] = v.w;
    }
}

// Load a BK x BN tile of row-major W (leading dim ldw) into Ws[BK][BNP].
__device__ __forceinline__ void load_w_tile(float (*Ws)[BNP],
                                            const float* __restrict__ W,
                                            int k0, int n0, int ldw, int tid) {
    int kk = tid >> 4;                      // 0 .. 15
    int nq = tid & 15;                      // 0 .. 15
    const float4 v = *reinterpret_cast<const float4*>(
        W + (size_t)(k0 + kk) * ldw + n0 + nq * 4);
    *reinterpret_cast<float4*>(&Ws[kk][nq * 4]) = v;
}

// ---------------------------------------------------------------------------
// Layer 1: pre1 = [x0|x1] @ W1[0:512,:]  (t column + bias folded in epilogue)
//   h1  = relu(pre1 + t*W1[512,:] + b1)
//   dh1 = (pre1' > 0) ? W1[512,:] : 0
// ---------------------------------------------------------------------------
__global__ __launch_bounds__(NTHREADS, 2)
void layer1_kernel(const float* __restrict__ x0,
                   const float* __restrict__ x1,
                   const float* __restrict__ t,
                   const float* __restrict__ W1,
                   const float* __restrict__ b1) {
    __shared__ __align__(16) float As[BK][BMP];
    __shared__ __align__(16) float Ws[BK][BNP];

    const int tid = threadIdx.x;
    const int ty = tid >> 4;            // 0..15 -> 8 rows each
    const int tx = tid & 15;            // 0..15 -> 4 cols each
    const int row0 = blockIdx.y * BM;
    const int n0   = blockIdx.x * BN;

    unsigned long long acc2[4][4];
#pragma unroll
    for (int rp = 0; rp < 4; ++rp)
#pragma unroll
        for (int c = 0; c < 4; ++c) acc2[rp][c] = 0ULL;

    for (int kt = 0; kt < 2 * SDIM / BK; ++kt) {   // 32 tiles of 16 over K=512
        const float* src = (kt < SDIM / BK) ? x0 : x1;
        const int ksrc = (kt & (SDIM / BK - 1)) * BK;
        load_a_tile(As, src, row0, ksrc, SDIM, tid);
        load_w_tile(Ws, W1, kt * BK, n0, HID, tid);
        __syncthreads();
#pragma unroll
        for (int kk = 0; kk < BK; ++kk) {
            const ulonglong2 A0 = *reinterpret_cast<const ulonglong2*>(&As[kk][ty * 8]);
            const ulonglong2 A1 = *reinterpret_cast<const ulonglong2*>(&As[kk][ty * 8 + 4]);
            const float4 wv = *reinterpret_cast<const float4*>(&Ws[kk][tx * 4]);
            unsigned long long ap[4] = {A0.x, A0.y, A1.x, A1.y};
            unsigned long long w2[4] = {bcast2(wv.x), bcast2(wv.y), bcast2(wv.z), bcast2(wv.w)};
#pragma unroll
            for (int rp = 0; rp < 4; ++rp)
#pragma unroll
                for (int c = 0; c < 4; ++c) fma2(acc2[rp][c], ap[rp], w2[c]);
        }
        __syncthreads();
    }

    // Epilogue
    const float4 bv = *reinterpret_cast<const float4*>(&b1[n0 + tx * 4]);
    const float4 wl = *reinterpret_cast<const float4*>(&W1[(size_t)512 * HID + n0 + tx * 4]);
    const float bva[4] = {bv.x, bv.y, bv.z, bv.w};
    const float wla[4] = {wl.x, wl.y, wl.z, wl.w};

#pragma unroll
    for (int rp = 0; rp < 4; ++rp) {
        float lo[4], hi[4];
#pragma unroll
        for (int c = 0; c < 4; ++c) unpack2(acc2[rp][c], lo[c], hi[c]);
#pragma unroll
        for (int half = 0; half < 2; ++half) {
            const int m = row0 + ty * 8 + rp * 2 + half;
            const float tv = t[m];
            float hval[4], dval[4];
#pragma unroll
            for (int c = 0; c < 4; ++c) {
                const float pre = (half ? hi[c] : lo[c]) + tv * wla[c] + bva[c];
                hval[c] = fmaxf(pre, 0.f);
                dval[c] = (pre > 0.f) ? wla[c] : 0.f;
            }
            const size_t o = (size_t)m * HID + n0 + tx * 4;
            *reinterpret_cast<float4*>(&g_hA[o])  = make_float4(hval[0], hval[1], hval[2], hval[3]);
            *reinterpret_cast<float4*>(&g_dhA[o]) = make_float4(dval[0], dval[1], dval[2], dval[3]);
        }
    }
}

// ---------------------------------------------------------------------------
// Middle layers (2, 3): dual GEMM sharing W tiles.
// DIR=0: A -> B (W2);  DIR=1: B -> A (W3)
// ---------------------------------------------------------------------------
template <int DIR>
__global__ __launch_bounds__(NTHREADS, 2)
void mid_kernel(const float* __restrict__ W, const float* __restrict__ b) {
    const float* __restrict__ hin   = (DIR == 0) ? g_hA  : g_hB;
    const float* __restrict__ dhin  = (DIR == 0) ? g_dhA : g_dhB;
    float* __restrict__ hout  = (DIR == 0) ? g_hB  : g_hA;
    float* __restrict__ dhout = (DIR == 0) ? g_dhB : g_dhA;

    __shared__ __align__(16) float As [BK][BMP];
    __shared__ __align__(16) float dAs[BK][BMP];
    __shared__ __align__(16) float Ws [BK][BNP];

    const int tid = threadIdx.x;
    const int ty = tid >> 4;
    const int tx = tid & 15;
    const int row0 = blockIdx.y * BM;
    const int n0   = blockIdx.x * BN;

    unsigned long long acc2[4][4], dacc2[4][4];
#pragma unroll
    for (int rp = 0; rp < 4; ++rp)
#pragma unroll
        for (int c = 0; c < 4; ++c) { acc2[rp][c] = 0ULL; dacc2[rp][c] = 0ULL; }

    for (int k0 = 0; k0 < HID; k0 += BK) {
        load_a_tile(As,  hin,  row0, k0, HID, tid);
        load_a_tile(dAs, dhin, row0, k0, HID, tid);
        load_w_tile(Ws, W, k0, n0, HID, tid);
        __syncthreads();
#pragma unroll
        for (int kk = 0; kk < BK; ++kk) {
            const ulonglong2 A0 = *reinterpret_cast<const ulonglong2*>(&As [kk][ty * 8]);
            const ulonglong2 A1 = *reinterpret_cast<const ulonglong2*>(&As [kk][ty * 8 + 4]);
            const ulonglong2 D0 = *reinterpret_cast<const ulonglong2*>(&dAs[kk][ty * 8]);
            const ulonglong2 D1 = *reinterpret_cast<const ulonglong2*>(&dAs[kk][ty * 8 + 4]);
            const float4 wv = *reinterpret_cast<const float4*>(&Ws[kk][tx * 4]);
            unsigned long long ap[4] = {A0.x, A0.y, A1.x, A1.y};
            unsigned long long dp[4] = {D0.x, D0.y, D1.x, D1.y};
            unsigned long long w2[4] = {bcast2(wv.x), bcast2(wv.y), bcast2(wv.z), bcast2(wv.w)};
#pragma unroll
            for (int rp = 0; rp < 4; ++rp)
#pragma unroll
                for (int c = 0; c < 4; ++c) {
                    fma2(acc2 [rp][c], ap[rp], w2[c]);
                    fma2(dacc2[rp][c], dp[rp], w2[c]);
                }
        }
        __syncthreads();
    }

    const float4 bv = *reinterpret_cast<const float4*>(&b[n0 + tx * 4]);
    const float bva[4] = {bv.x, bv.y, bv.z, bv.w};

#pragma unroll
    for (int rp = 0; rp < 4; ++rp) {
        float lo[4], hi[4], dlo[4], dhi[4];
#pragma unroll
        for (int c = 0; c < 4; ++c) {
            unpack2(acc2 [rp][c], lo[c],  hi[c]);
            unpack2(dacc2[rp][c], dlo[c], dhi[c]);
        }
#pragma unroll
        for (int half = 0; half < 2; ++half) {
            const int m = row0 + ty * 8 + rp * 2 + half;
            float hval[4], dval[4];
#pragma unroll
            for (int c = 0; c < 4; ++c) {
                const float pre = (half ? hi[c] : lo[c]) + bva[c];
                const float dd  = (half ? dhi[c] : dlo[c]);
                hval[c] = fmaxf(pre, 0.f);
                dval[c] = (pre > 0.f) ? dd : 0.f;
            }
            const size_t o = (size_t)m * HID + n0 + tx * 4;
            *reinterpret_cast<float4*>(&hout[o])  = make_float4(hval[0], hval[1], hval[2], hval[3]);
            *reinterpret_cast<float4*>(&dhout[o]) = make_float4(dval[0], dval[1], dval[2], dval[3]);
        }
    }
}

// ---------------------------------------------------------------------------
// Layer 4 + interpolant combine. Reads (g_hA, g_dhA) (written by mid<1>).
// out[0 : B*256)          = xt
// out[B*256 : 2*B*256)    = dt_xt
// ---------------------------------------------------------------------------
__global__ __launch_bounds__(NTHREADS, 2)
void layer4_kernel(const float* __restrict__ W4, const float* __restrict__ b4,
                   const float* __restrict__ x0, const float* __restrict__ x1,
                   const float* __restrict__ t,  float* __restrict__ out) {
    __shared__ __align__(16) float As [BK][BMP];
    __shared__ __align__(16) float dAs[BK][BMP];
    __shared__ __align__(16) float Ws [BK][BNP];

    const int tid = threadIdx.x;
    const int ty = tid >> 4;
    const int tx = tid & 15;
    const int row0 = blockIdx.y * BM;
    const int n0   = blockIdx.x * BN;

    unsigned long long acc2[4][4], dacc2[4][4];
#pragma unroll
    for (int rp = 0; rp < 4; ++rp)
#pragma unroll
        for (int c = 0; c < 4; ++c) { acc2[rp][c] = 0ULL; dacc2[rp][c] = 0ULL; }

    for (int k0 = 0; k0 < HID; k0 += BK) {
        load_a_tile(As,  g_hA,  row0, k0, HID, tid);
        load_a_tile(dAs, g_dhA, row0, k0, HID, tid);
        load_w_tile(Ws, W4, k0, n0, SDIM, tid);
        __syncthreads();
#pragma unroll
        for (int kk = 0; kk < BK; ++kk) {
            const ulonglong2 A0 = *reinterpret_cast<const ulonglong2*>(&As [kk][ty * 8]);
            const ulonglong2 A1 = *reinterpret_cast<const ulonglong2*>(&As [kk][ty * 8 + 4]);
            const ulonglong2 D0 = *reinterpret_cast<const ulonglong2*>(&dAs[kk][ty * 8]);
            const ulonglong2 D1 = *reinterpret_cast<const ulonglong2*>(&dAs[kk][ty * 8 + 4]);
            const float4 wv = *reinterpret_cast<const float4*>(&Ws[kk][tx * 4]);
            unsigned long long ap[4] = {A0.x, A0.y, A1.x, A1.y};
            unsigned long long dp[4] = {D0.x, D0.y, D1.x, D1.y};
            unsigned long long w2[4] = {bcast2(wv.x), bcast2(wv.y), bcast2(wv.z), bcast2(wv.w)};
#pragma unroll
            for (int rp = 0; rp < 4; ++rp)
#pragma unroll
                for (int c = 0; c < 4; ++c) {
                    fma2(acc2 [rp][c], ap[rp], w2[c]);
                    fma2(dacc2[rp][c], dp[rp], w2[c]);
                }
        }
        __syncthreads();
    }

    const float4 bv = *reinterpret_cast<const float4*>(&b4[n0 + tx * 4]);
    const float bva[4] = {bv.x, bv.y, bv.z, bv.w};
    const size_t dt_off = (size_t)BATCH * SDIM;

#pragma unroll
    for (int rp = 0; rp < 4; ++rp) {
        float lo[4], hi[4], dlo[4], dhi[4];
#pragma unroll
        for (int c = 0; c < 4; ++c) {
            unpack2(acc2 [rp][c], lo[c],  hi[c]);
            unpack2(dacc2[rp][c], dlo[c], dhi[c]);
        }
#pragma unroll
        for (int half = 0; half < 2; ++half) {
            const int m = row0 + ty * 8 + rp * 2 + half;
            const float tv = t[m];
            const float tc = tv * (1.f - tv);
            const size_t xo = (size_t)m * SDIM + n0 + tx * 4;
            const float4 x0v = *reinterpret_cast<const float4*>(&x0[xo]);
            const float4 x1v = *reinterpret_cast<const float4*>(&x1[xo]);
            const float x0a[4] = {x0v.x, x0v.y, x0v.z, x0v.w};
            const float x1a[4] = {x1v.x, x1v.y, x1v.z, x1v.w};
            float xt[4], dxt[4];
#pragma unroll
            for (int c = 0; c < 4; ++c) {
                const float fnn = (half ? hi[c] : lo[c]) + bva[c];
                const float dtf = (half ? dhi[c] : dlo[c]);
                xt[c]  = (1.f - tv) * x0a[c] + tv * x1a[c] + tc * fnn;
                dxt[c] = x1a[c] - x0a[c] + (1.f - 2.f * tv) * fnn + tc * dtf;
            }
            *reinterpret_cast<float4*>(&out[xo])          = make_float4(xt[0],  xt[1],  xt[2],  xt[3]);
            *reinterpret_cast<float4*>(&out[dt_off + xo]) = make_float4(dxt[0], dxt[1], dxt[2], dxt[3]);
        }
    }
}

// ---------------------------------------------------------------------------
// Launch
// ---------------------------------------------------------------------------
extern "C" void kernel_launch(void* const* d_in, const int* in_sizes, int n_in,
                              void* d_out, int out_size) {
    (void)in_sizes; (void)n_in; (void)out_size;
    const float* x0 = (const float*)d_in[0];
    const float* x1 = (const float*)d_in[1];
    const float* t  = (const float*)d_in[2];
    const float* W1 = (const float*)d_in[3];
    const float* b1 = (const float*)d_in[4];
    const float* W2 = (const float*)d_in[5];
    const float* b2 = (const float*)d_in[6];
    const float* W3 = (const float*)d_in[7];
    const float* b3 = (const float*)d_in[8];
    const float* W4 = (const float*)d_in[9];
    const float* b4 = (const float*)d_in[10];
    float* out = (float*)d_out;

    dim3 block(NTHREADS);
    dim3 grid_mid(HID / BN, BATCH / BM);    // (16, 512)
    dim3 grid_out(SDIM / BN, BATCH / BM);   // (4, 512)

    layer1_kernel<<<grid_mid, block>>>(x0, x1, t, W1, b1);
    mid_kernel<0><<<grid_mid, block>>>(W2, b2);
    mid_kernel<1><<<grid_mid, block>>>(W3, b3);
    layer4_kernel<<<grid_out, block>>>(W4, b4, x0, x1, t, out);
}

// round 3
// speedup vs baseline: 3.4396x; 3.4396x over previous
#include <cuda_runtime.h>
#include <cuda_bf16.h>
#include <cstdint>
#include <cstddef>

using bf16 = __nv_bfloat16;

// ---------------------------------------------------------------------------
// AddInterpolant via mma.sync (baseline PTX only — tcgen05 is sm_103a-gated
// and this bench's PTX target is plain sm_103).
//
// Value stream: bf16 hi/lo split, 3 MMA products (rel err ~1e-5).
// Tangent stream: single bf16 product (contribution to output is tiny).
// ---------------------------------------------------------------------------

constexpr int BATCH = 65536;
constexpr int SDIM  = 256;
constexpr int HID   = 1024;

constexpr int BM   = 128;
constexpr int BN   = 64;
constexpr int BKC  = 64;            // k per stage
constexpr int NT   = 256;           // 8 warps
constexpr int NSTG = 3;
constexpr int ATB  = BM * 128;      // 16384 B  (128 rows x 128B)
constexpr int BTB  = BN * 128;      // 8192 B

// ---------------------------------------------------------------------------
// Scratch (static device memory)
// ---------------------------------------------------------------------------
__device__ __align__(256) bf16 g_z_hi[(size_t)BATCH * 512];
__device__ __align__(256) bf16 g_z_lo[(size_t)BATCH * 512];

__device__ __align__(256) bf16 g_hA_hi[(size_t)BATCH * HID];
__device__ __align__(256) bf16 g_hA_lo[(size_t)BATCH * HID];
__device__ __align__(256) bf16 g_hB_hi[(size_t)BATCH * HID];
__device__ __align__(256) bf16 g_hB_lo[(size_t)BATCH * HID];
__device__ __align__(256) bf16 g_dA  [(size_t)BATCH * HID];
__device__ __align__(256) bf16 g_dB  [(size_t)BATCH * HID];

// Transposed + split weights: Wt[n][k]
__device__ __align__(256) bf16 g_wt1_hi[(size_t)HID * 512];
__device__ __align__(256) bf16 g_wt1_lo[(size_t)HID * 512];
__device__ __align__(256) bf16 g_wt2_hi[(size_t)HID * HID];
__device__ __align__(256) bf16 g_wt2_lo[(size_t)HID * HID];
__device__ __align__(256) bf16 g_wt3_hi[(size_t)HID * HID];
__device__ __align__(256) bf16 g_wt3_lo[(size_t)HID * HID];
__device__ __align__(256) bf16 g_wt4_hi[(size_t)SDIM * HID];
__device__ __align__(256) bf16 g_wt4_lo[(size_t)SDIM * HID];

// ---------------------------------------------------------------------------
// Helpers
// ---------------------------------------------------------------------------
__device__ __forceinline__ uint32_t smem_u32(const void* p) {
    uint32_t a;
    asm("{ .reg .u64 t; cvta.to.shared.u64 t, %1; cvt.u32.u64 %0, t; }"
        : "=r"(a) : "l"(p));
    return a;
}
__device__ __forceinline__ void cpasync16(uint32_t s, const void* g) {
    asm volatile("cp.async.cg.shared.global [%0], [%1], 16;"
                 :: "r"(s), "l"(g) : "memory");
}
__device__ __forceinline__ void cp_commit() {
    asm volatile("cp.async.commit_group;" ::: "memory");
}
template <int N>
__device__ __forceinline__ void cp_wait() {
    asm volatile("cp.async.wait_group %0;" :: "n"(N) : "memory");
}
__device__ __forceinline__ void ldsm4(uint32_t addr, uint32_t r[4]) {
    asm volatile("ldmatrix.sync.aligned.m8n8.x4.shared.b16 {%0,%1,%2,%3}, [%4];"
                 : "=r"(r[0]), "=r"(r[1]), "=r"(r[2]), "=r"(r[3]) : "r"(addr));
}
__device__ __forceinline__ void mma_bf16(float c[4], const uint32_t a[4],
                                         const uint32_t b[2]) {
    asm("mma.sync.aligned.m16n8k16.row.col.f32.bf16.bf16.f32 "
        "{%0,%1,%2,%3}, {%4,%5,%6,%7}, {%8,%9}, {%0,%1,%2,%3};"
        : "+f"(c[0]), "+f"(c[1]), "+f"(c[2]), "+f"(c[3])
        : "r"(a[0]), "r"(a[1]), "r"(a[2]), "r"(a[3]), "r"(b[0]), "r"(b[1]));
}
__device__ __forceinline__ uint32_t swzoff(int row, int chunk) {
    return (uint32_t)(row * 128 + ((chunk ^ (row & 7)) << 4));
}
__device__ __forceinline__ void split_bf(float x, bf16& hi, bf16& lo) {
    hi = __float2bfloat16_rn(x);
    lo = __float2bfloat16_rn(x - __bfloat162float(hi));
}
__device__ __forceinline__ uint32_t pack2(bf16 a, bf16 b) {
    __nv_bfloat162 t2(a, b);
    return *reinterpret_cast<uint32_t*>(&t2);
}

// ---------------------------------------------------------------------------
// Prep kernels
// ---------------------------------------------------------------------------
__global__ void split_w_kernel(const float* __restrict__ W, bf16* __restrict__ hi,
                               bf16* __restrict__ lo, int K, int N) {
    int id = blockIdx.x * blockDim.x + threadIdx.x;
    if (id >= K * N) return;
    int k = id / N, n = id % N;
    bf16 h, l;
    split_bf(W[id], h, l);
    hi[(size_t)n * K + k] = h;
    lo[(size_t)n * K + k] = l;
}

__global__ void split_z_kernel(const float* __restrict__ x0, const float* __restrict__ x1) {
    int id = blockIdx.x * blockDim.x + threadIdx.x;
    if (id >= BATCH * SDIM) return;
    int b = id / SDIM, c = id % SDIM;
    bf16 h, l;
    split_bf(x0[id], h, l);
    g_z_hi[(size_t)b * 512 + c] = h;
    g_z_lo[(size_t)b * 512 + c] = l;
    split_bf(x1[id], h, l);
    g_z_hi[(size_t)b * 512 + 256 + c] = h;
    g_z_lo[(size_t)b * 512 + 256 + c] = l;
}

// ---------------------------------------------------------------------------
// GEMM kernel. MODE: 0=layer1 (no tangent GEMM), 1=mid, 2=layer4+combine.
// ---------------------------------------------------------------------------
template <int MODE, int NC, bool TG, int LDA, int LDB>
__global__ __launch_bounds__(NT, 1)
void gemm3_kernel(const bf16* __restrict__ Ahi, const bf16* __restrict__ Alo,
                  const bf16* __restrict__ Ad,
                  const bf16* __restrict__ Bhi, const bf16* __restrict__ Blo,
                  const float* __restrict__ bias,
                  const float* __restrict__ p0, const float* __restrict__ p1,
                  const float* __restrict__ p2,
                  bf16* __restrict__ ohh, bf16* __restrict__ ohl,
                  bf16* __restrict__ od, float* __restrict__ out) {
    extern __shared__ __align__(128) char smem[];
    constexpr int NA = TG ? 3 : 2;              // A-side tiles per stage
    constexpr int STAGE = NA * ATB + 2 * BTB;
    constexpr int OFF_BH = NA * ATB;
    constexpr int OFF_BL = OFF_BH + BTB;

    const int tid  = threadIdx.x;
    const int warp = tid >> 5;
    const int lane = tid & 31;
    const int wm = (warp & 3) * 32;
    const int wn = (warp >> 2) * 32;
    const int row0 = blockIdx.y * BM;
    const int n0   = blockIdx.x * BN;

    const uint32_t sb0 = smem_u32(smem);

    const char* gAh = (const char*)(Ahi + (size_t)row0 * LDA);
    const char* gAl = (const char*)(Alo + (size_t)row0 * LDA);
    const char* gAd = TG ? (const char*)(Ad + (size_t)row0 * LDA) : nullptr;
    const char* gBh = (const char*)(Bhi + (size_t)n0 * LDB);
    const char* gBl = (const char*)(Blo + (size_t)n0 * LDB);

    auto issue = [&](int c) {
        const uint32_t base = sb0 + (c % NSTG) * STAGE;
        const size_t kb = (size_t)c * (BKC * 2);
        // A tiles: 1024 16B chunks each, 4 per thread
#pragma unroll
        for (int i = 0; i < 4; ++i) {
            const int sid = i * NT + tid;
            const int row = sid >> 3;
            const int seg = sid & 7;
            const uint32_t so = swzoff(row, seg);
            const size_t go = (size_t)row * (LDA * 2) + kb + seg * 16;
            cpasync16(base + so, gAh + go);
            cpasync16(base + ATB + so, gAl + go);
            if (TG) cpasync16(base + 2 * ATB + so, gAd + go);
        }
        // B tiles: 512 chunks each, 2 per thread
#pragma unroll
        for (int i = 0; i < 2; ++i) {
            const int sid = i * NT + tid;
            const int row = sid >> 3;
            const int seg = sid & 7;
            const uint32_t so = swzoff(row, seg);
            const size_t go = (size_t)row * (LDB * 2) + kb + seg * 16;
            cpasync16(base + OFF_BH + so, gBh + go);
            cpasync16(base + OFF_BL + so, gBl + go);
        }
        cp_commit();
    };

    float accV[2][4][4];
    float accD[2][4][4];
#pragma unroll
    for (int mt = 0; mt < 2; ++mt)
#pragma unroll
        for (int nt = 0; nt < 4; ++nt)
#pragma unroll
            for (int j = 0; j < 4; ++j) { accV[mt][nt][j] = 0.f; accD[mt][nt][j] = 0.f; }

    issue(0);
    issue(1);

    // per-lane ldmatrix offsets (row/chunk pattern constant across stages)
    const int ag = lane >> 3;
    const int arow0 = wm + (ag & 1) * 8 + (lane & 7);     // + mt*16
    const int acb = ag >> 1;                              // + 2*ks
    const int brow0 = wn + ((lane >> 3) >= 2 ? 8 : 0) + (lane & 7);  // + np*16
    const int bcb = (lane >> 3) & 1;                      // + 2*ks

#pragma unroll 1
    for (int c = 0; c < NC; ++c) {
        if (c + 2 < NC) { issue(c + 2); cp_wait<2>(); }
        else if (c + 1 < NC) { cp_wait<1>(); }
        else { cp_wait<0>(); }
        __syncthreads();

        const uint32_t base = sb0 + (c % NSTG) * STAGE;
#pragma unroll
        for (int ks = 0; ks < 4; ++ks) {
            uint32_t avh[2][4], avl[2][4], ad[2][4];
            uint32_t bh[4][2], bl[4][2];
#pragma unroll
            for (int mt = 0; mt < 2; ++mt) {
                const uint32_t off = swzoff(arow0 + mt * 16, acb + 2 * ks);
                ldsm4(base + off, avh[mt]);
                ldsm4(base + ATB + off, avl[mt]);
                if (TG) ldsm4(base + 2 * ATB + off, ad[mt]);
            }
#pragma unroll
            for (int np = 0; np < 2; ++np) {
                const uint32_t off = swzoff(brow0 + np * 16, bcb + 2 * ks);
                uint32_t r[4];
                ldsm4(base + OFF_BH + off, r);
                bh[np * 2][0] = r[0]; bh[np * 2][1] = r[1];
                bh[np * 2 + 1][0] = r[2]; bh[np * 2 + 1][1] = r[3];
                ldsm4(base + OFF_BL + off, r);
                bl[np * 2][0] = r[0]; bl[np * 2][1] = r[1];
                bl[np * 2 + 1][0] = r[2]; bl[np * 2 + 1][1] = r[3];
            }
#pragma unroll
            for (int mt = 0; mt < 2; ++mt)
#pragma unroll
                for (int nt = 0; nt < 4; ++nt) {
                    mma_bf16(accV[mt][nt], avh[mt], bh[nt]);
                    mma_bf16(accV[mt][nt], avl[mt], bh[nt]);
                    mma_bf16(accV[mt][nt], avh[mt], bl[nt]);
                    if (TG) mma_bf16(accD[mt][nt], ad[mt], bh[nt]);
                }
        }
        __syncthreads();
    }

    // ---- Epilogue ----
    const int q2 = 2 * (lane & 3);
#pragma unroll
    for (int mt = 0; mt < 2; ++mt) {
#pragma unroll
        for (int nt = 0; nt < 4; ++nt) {
            const int col = n0 + wn + nt * 8 + q2;
            const float2 bv = *(const float2*)&bias[col];
#pragma unroll
            for (int cp = 0; cp < 2; ++cp) {
                const int row = row0 + wm + mt * 16 + (lane >> 2) + cp * 8;
                const float a0 = accV[mt][nt][cp * 2 + 0];
                const float a1 = accV[mt][nt][cp * 2 + 1];

                if (MODE == 0) {
                    const float2 wv = *(const float2*)&p0[col];
                    const float tv = p1[row];
                    const float pre0 = a0 + tv * wv.x + bv.x;
                    const float pre1 = a1 + tv * wv.y + bv.y;
                    bf16 h0h, h0l, h1h, h1l;
                    split_bf(fmaxf(pre0, 0.f), h0h, h0l);
                    split_bf(fmaxf(pre1, 0.f), h1h, h1l);
                    const bf16 d0 = __float2bfloat16_rn(pre0 > 0.f ? wv.x : 0.f);
                    const bf16 d1 = __float2bfloat16_rn(pre1 > 0.f ? wv.y : 0.f);
                    const size_t o = (size_t)row * HID + col;
                    *(uint32_t*)&ohh[o] = pack2(h0h, h1h);
                    *(uint32_t*)&ohl[o] = pack2(h0l, h1l);
                    *(uint32_t*)&od[o]  = pack2(d0, d1);
                } else if (MODE == 1) {
                    const float pre0 = a0 + bv.x;
                    const float pre1 = a1 + bv.y;
                    bf16 h0h, h0l, h1h, h1l;
                    split_bf(fmaxf(pre0, 0.f), h0h, h0l);
                    split_bf(fmaxf(pre1, 0.f), h1h, h1l);
                    const bf16 d0 = __float2bfloat16_rn(pre0 > 0.f ? accD[mt][nt][cp * 2 + 0] : 0.f);
                    const bf16 d1 = __float2bfloat16_rn(pre1 > 0.f ? accD[mt][nt][cp * 2 + 1] : 0.f);
                    const size_t o = (size_t)row * HID + col;
                    *(uint32_t*)&ohh[o] = pack2(h0h, h1h);
                    *(uint32_t*)&ohl[o] = pack2(h0l, h1l);
                    *(uint32_t*)&od[o]  = pack2(d0, d1);
                } else {
                    const float fnn0 = a0 + bv.x;
                    const float fnn1 = a1 + bv.y;
                    const float dt0 = accD[mt][nt][cp * 2 + 0];
                    const float dt1 = accD[mt][nt][cp * 2 + 1];
                    const float tv = p2[row];
                    const float tc = tv * (1.f - tv);
                    const float om2t = 1.f - 2.f * tv;
                    const size_t xo = (size_t)row * SDIM + col;
                    const float2 x0v = *(const float2*)&p0[xo];
                    const float2 x1v = *(const float2*)&p1[xo];
                    float2 xt, dxt;
                    xt.x = (1.f - tv) * x0v.x + tv * x1v.x + tc * fnn0;
                    xt.y = (1.f - tv) * x0v.y + tv * x1v.y + tc * fnn1;
                    dxt.x = x1v.x - x0v.x + om2t * fnn0 + tc * dt0;
                    dxt.y = x1v.y - x0v.y + om2t * fnn1 + tc * dt1;
                    *(float2*)&out[xo] = xt;
                    *(float2*)&out[(size_t)BATCH * SDIM + xo] = dxt;
                }
            }
        }
    }
}

// ---------------------------------------------------------------------------
// Launch
// ---------------------------------------------------------------------------
extern "C" void kernel_launch(void* const* d_in, const int* in_sizes, int n_in,
                              void* d_out, int out_size) {
    (void)in_sizes; (void)n_in; (void)out_size;
    const float* x0 = (const float*)d_in[0];
    const float* x1 = (const float*)d_in[1];
    const float* t  = (const float*)d_in[2];
    const float* W1 = (const float*)d_in[3];
    const float* b1 = (const float*)d_in[4];
    const float* W2 = (const float*)d_in[5];
    const float* b2 = (const float*)d_in[6];
    const float* W3 = (const float*)d_in[7];
    const float* b3 = (const float*)d_in[8];
    const float* W4 = (const float*)d_in[9];
    const float* b4 = (const float*)d_in[10];
    float* out = (float*)d_out;

    bf16 *zH, *zL, *hAH, *hAL, *hBH, *hBL, *dA, *dB;
    bf16 *w1H, *w1L, *w2H, *w2L, *w3H, *w3L, *w4H, *w4L;
    cudaGetSymbolAddress((void**)&zH, g_z_hi);   cudaGetSymbolAddress((void**)&zL, g_z_lo);
    cudaGetSymbolAddress((void**)&hAH, g_hA_hi); cudaGetSymbolAddress((void**)&hAL, g_hA_lo);
    cudaGetSymbolAddress((void**)&hBH, g_hB_hi); cudaGetSymbolAddress((void**)&hBL, g_hB_lo);
    cudaGetSymbolAddress((void**)&dA, g_dA);     cudaGetSymbolAddress((void**)&dB, g_dB);
    cudaGetSymbolAddress((void**)&w1H, g_wt1_hi); cudaGetSymbolAddress((void**)&w1L, g_wt1_lo);
    cudaGetSymbolAddress((void**)&w2H, g_wt2_hi); cudaGetSymbolAddress((void**)&w2L, g_wt2_lo);
    cudaGetSymbolAddress((void**)&w3H, g_wt3_hi); cudaGetSymbolAddress((void**)&w3L, g_wt3_lo);
    cudaGetSymbolAddress((void**)&w4H, g_wt4_hi); cudaGetSymbolAddress((void**)&w4L, g_wt4_lo);

    constexpr int SM_L1  = NSTG * (2 * ATB + 2 * BTB);   // 3 * 48KB = 147456
    constexpr int SM_MID = NSTG * (3 * ATB + 2 * BTB);   // 3 * 64KB = 196608

    cudaFuncSetAttribute(gemm3_kernel<0, 8, false, 512, 512>,
                         cudaFuncAttributeMaxDynamicSharedMemorySize, SM_L1);
    cudaFuncSetAttribute(gemm3_kernel<1, 16, true, 1024, 1024>,
                         cudaFuncAttributeMaxDynamicSharedMemorySize, SM_MID);
    cudaFuncSetAttribute(gemm3_kernel<2, 16, true, 1024, 1024>,
                         cudaFuncAttributeMaxDynamicSharedMemorySize, SM_MID);

    split_z_kernel<<<(BATCH * SDIM + 255) / 256, 256>>>(x0, x1);
    split_w_kernel<<<(512 * HID + 255) / 256, 256>>>(W1, w1H, w1L, 512, HID);
    split_w_kernel<<<(HID * HID + 255) / 256, 256>>>(W2, w2H, w2L, HID, HID);
    split_w_kernel<<<(HID * HID + 255) / 256, 256>>>(W3, w3H, w3L, HID, HID);
    split_w_kernel<<<(HID * SDIM + 255) / 256, 256>>>(W4, w4H, w4L, HID, SDIM);

    dim3 blk(NT);
    dim3 grid_hid(HID / BN, BATCH / BM);   // (16, 512)
    dim3 grid_out(SDIM / BN, BATCH / BM);  // (4, 512)

    // layer 1: value GEMM over z (K=512); tangent analytic in epilogue
    gemm3_kernel<0, 8, false, 512, 512><<<grid_hid, blk, SM_L1>>>(
        zH, zL, nullptr, w1H, w1L, b1,
        W1 + (size_t)512 * HID, t, nullptr,
        hAH, hAL, dA, nullptr);

    // layer 2: A -> B
    gemm3_kernel<1, 16, true, 1024, 1024><<<grid_hid, blk, SM_MID>>>(
        hAH, hAL, dA, w2H, w2L, b2,
        nullptr, nullptr, nullptr,
        hBH, hBL, dB, nullptr);

    // layer 3: B -> A
    gemm3_kernel<1, 16, true, 1024, 1024><<<grid_hid, blk, SM_MID>>>(
        hBH, hBL, dB, w3H, w3L, b3,
        nullptr, nullptr, nullptr,
        hAH, hAL, dA, nullptr);

    // layer 4 + interpolant combine
    gemm3_kernel<2, 16, true, 1024, 1024><<<grid_out, blk, SM_MID>>>(
        hAH, hAL, dA, w4H, w4L, b4,
        x0, x1, t,
        nullptr, nullptr, nullptr, out);
}

// round 4
// speedup vs baseline: 3.8577x; 1.1216x over previous
#include <cuda_runtime.h>
#include <cuda_bf16.h>
#include <cstdint>
#include <cstddef>

using bf16 = __nv_bfloat16;

// ---------------------------------------------------------------------------
// AddInterpolant via mma.sync bf16 (baseline PTX; tcgen05 unavailable at this
// bench's ptxas target). Value stream: hi/lo split, 3 products. Tangent:
// single bf16 product. R4: BN=128 tiles (halved A-panel L2 traffic, better
// smem reuse per HMMA), 2-stage cp.async pipeline.
// ---------------------------------------------------------------------------

constexpr int BATCH = 65536;
constexpr int SDIM  = 256;
constexpr int HID   = 1024;

constexpr int BM   = 128;
constexpr int BN   = 128;
constexpr int BKC  = 64;            // k per stage
constexpr int NT   = 256;           // 8 warps: 2 (m) x 4 (n)
constexpr int NSTG = 2;
constexpr int ATB  = BM * 128;      // 16384 B per A tile (128 rows x 128B)
constexpr int BTB  = BN * 128;      // 16384 B per B tile

// ---------------------------------------------------------------------------
// Scratch (static device memory)
// ---------------------------------------------------------------------------
__device__ __align__(256) bf16 g_z_hi[(size_t)BATCH * 512];
__device__ __align__(256) bf16 g_z_lo[(size_t)BATCH * 512];

__device__ __align__(256) bf16 g_hA_hi[(size_t)BATCH * HID];
__device__ __align__(256) bf16 g_hA_lo[(size_t)BATCH * HID];
__device__ __align__(256) bf16 g_hB_hi[(size_t)BATCH * HID];
__device__ __align__(256) bf16 g_hB_lo[(size_t)BATCH * HID];
__device__ __align__(256) bf16 g_dA  [(size_t)BATCH * HID];
__device__ __align__(256) bf16 g_dB  [(size_t)BATCH * HID];

// Transposed + split weights: Wt[n][k]
__device__ __align__(256) bf16 g_wt1_hi[(size_t)HID * 512];
__device__ __align__(256) bf16 g_wt1_lo[(size_t)HID * 512];
__device__ __align__(256) bf16 g_wt2_hi[(size_t)HID * HID];
__device__ __align__(256) bf16 g_wt2_lo[(size_t)HID * HID];
__device__ __align__(256) bf16 g_wt3_hi[(size_t)HID * HID];
__device__ __align__(256) bf16 g_wt3_lo[(size_t)HID * HID];
__device__ __align__(256) bf16 g_wt4_hi[(size_t)SDIM * HID];
__device__ __align__(256) bf16 g_wt4_lo[(size_t)SDIM * HID];

// ---------------------------------------------------------------------------
// Helpers
// ---------------------------------------------------------------------------
__device__ __forceinline__ uint32_t smem_u32(const void* p) {
    uint32_t a;
    asm("{ .reg .u64 t; cvta.to.shared.u64 t, %1; cvt.u32.u64 %0, t; }"
        : "=r"(a) : "l"(p));
    return a;
}
__device__ __forceinline__ void cpasync16(uint32_t s, const void* g) {
    asm volatile("cp.async.cg.shared.global [%0], [%1], 16;"
                 :: "r"(s), "l"(g) : "memory");
}
__device__ __forceinline__ void cp_commit() {
    asm volatile("cp.async.commit_group;" ::: "memory");
}
template <int N>
__device__ __forceinline__ void cp_wait() {
    asm volatile("cp.async.wait_group %0;" :: "n"(N) : "memory");
}
__device__ __forceinline__ void ldsm4(uint32_t addr, uint32_t r[4]) {
    asm volatile("ldmatrix.sync.aligned.m8n8.x4.shared.b16 {%0,%1,%2,%3}, [%4];"
                 : "=r"(r[0]), "=r"(r[1]), "=r"(r[2]), "=r"(r[3]) : "r"(addr));
}
__device__ __forceinline__ void mma_bf16(float c[4], const uint32_t a[4],
                                         const uint32_t b[2]) {
    asm("mma.sync.aligned.m16n8k16.row.col.f32.bf16.bf16.f32 "
        "{%0,%1,%2,%3}, {%4,%5,%6,%7}, {%8,%9}, {%0,%1,%2,%3};"
        : "+f"(c[0]), "+f"(c[1]), "+f"(c[2]), "+f"(c[3])
        : "r"(a[0]), "r"(a[1]), "r"(a[2]), "r"(a[3]), "r"(b[0]), "r"(b[1]));
}
__device__ __forceinline__ uint32_t swzoff(int row, int chunk) {
    return (uint32_t)(row * 128 + ((chunk ^ (row & 7)) << 4));
}
__device__ __forceinline__ void split_bf(float x, bf16& hi, bf16& lo) {
    hi = __float2bfloat16_rn(x);
    lo = __float2bfloat16_rn(x - __bfloat162float(hi));
}
__device__ __forceinline__ uint32_t pack2(bf16 a, bf16 b) {
    __nv_bfloat162 t2(a, b);
    return *reinterpret_cast<uint32_t*>(&t2);
}

// ---------------------------------------------------------------------------
// Prep kernels
// ---------------------------------------------------------------------------
__global__ void split_w_kernel(const float* __restrict__ W, bf16* __restrict__ hi,
                               bf16* __restrict__ lo, int K, int N) {
    int id = blockIdx.x * blockDim.x + threadIdx.x;
    if (id >= K * N) return;
    int k = id / N, n = id % N;
    bf16 h, l;
    split_bf(W[id], h, l);
    hi[(size_t)n * K + k] = h;
    lo[(size_t)n * K + k] = l;
}

__global__ void split_z_kernel(const float* __restrict__ x0, const float* __restrict__ x1) {
    int id = blockIdx.x * blockDim.x + threadIdx.x;
    if (id >= BATCH * SDIM) return;
    int b = id / SDIM, c = id % SDIM;
    bf16 h, l;
    split_bf(x0[id], h, l);
    g_z_hi[(size_t)b * 512 + c] = h;
    g_z_lo[(size_t)b * 512 + c] = l;
    split_bf(x1[id], h, l);
    g_z_hi[(size_t)b * 512 + 256 + c] = h;
    g_z_lo[(size_t)b * 512 + 256 + c] = l;
}

// ---------------------------------------------------------------------------
// GEMM kernel. MODE: 0=layer1 (no tangent GEMM), 1=mid, 2=layer4+combine.
// Warp layout: 2 (m) x 4 (n); warp tile 64 x 32.
// ---------------------------------------------------------------------------
template <int MODE, int NC, bool TG, int LDA, int LDB>
__global__ __launch_bounds__(NT, 1)
void gemm3_kernel(const bf16* __restrict__ Ahi, const bf16* __restrict__ Alo,
                  const bf16* __restrict__ Ad,
                  const bf16* __restrict__ Bhi, const bf16* __restrict__ Blo,
                  const float* __restrict__ bias,
                  const float* __restrict__ p0, const float* __restrict__ p1,
                  const float* __restrict__ p2,
                  bf16* __restrict__ ohh, bf16* __restrict__ ohl,
                  bf16* __restrict__ od, float* __restrict__ out) {
    extern __shared__ __align__(128) char smem[];
    constexpr int NA = TG ? 3 : 2;
    constexpr int STAGE = NA * ATB + 2 * BTB;
    constexpr int OFF_BH = NA * ATB;
    constexpr int OFF_BL = OFF_BH + BTB;

    const int tid  = threadIdx.x;
    const int warp = tid >> 5;
    const int lane = tid & 31;
    const int wm = (warp & 1) * 64;        // 2 warps along m
    const int wn = (warp >> 1) * 32;       // 4 warps along n
    const int row0 = blockIdx.y * BM;
    const int n0   = blockIdx.x * BN;

    const uint32_t sb0 = smem_u32(smem);

    const char* gAh = (const char*)(Ahi + (size_t)row0 * LDA);
    const char* gAl = (const char*)(Alo + (size_t)row0 * LDA);
    const char* gAd = TG ? (const char*)(Ad + (size_t)row0 * LDA) : nullptr;
    const char* gBh = (const char*)(Bhi + (size_t)n0 * LDB);
    const char* gBl = (const char*)(Blo + (size_t)n0 * LDB);

    auto issue = [&](int c) {
        const uint32_t base = sb0 + (c & (NSTG - 1)) * STAGE;
        const size_t kb = (size_t)c * (BKC * 2);
        // A and B tiles are each 128 rows x 128B = 1024 16B chunks, 4/thread
#pragma unroll
        for (int i = 0; i < 4; ++i) {
            const int sid = i * NT + tid;
            const int row = sid >> 3;
            const int seg = sid & 7;
            const uint32_t so = swzoff(row, seg);
            const size_t goA = (size_t)row * (LDA * 2) + kb + seg * 16;
            const size_t goB = (size_t)row * (LDB * 2) + kb + seg * 16;
            cpasync16(base + so, gAh + goA);
            cpasync16(base + ATB + so, gAl + goA);
            if (TG) cpasync16(base + 2 * ATB + so, gAd + goA);
            cpasync16(base + OFF_BH + so, gBh + goB);
            cpasync16(base + OFF_BL + so, gBl + goB);
        }
        cp_commit();
    };

    float accV[4][4][4];
    float accD[4][4][4];
#pragma unroll
    for (int mt = 0; mt < 4; ++mt)
#pragma unroll
        for (int nt = 0; nt < 4; ++nt)
#pragma unroll
            for (int j = 0; j < 4; ++j) { accV[mt][nt][j] = 0.f; if (TG) accD[mt][nt][j] = 0.f; }

    issue(0);

    // per-lane ldmatrix row/chunk pattern
    const int ag = lane >> 3;
    const int arow0 = wm + (ag & 1) * 8 + (lane & 7);            // + mt*16
    const int acb = ag >> 1;                                     // + 2*ks
    const int brow0 = wn + ((lane >> 3) >= 2 ? 8 : 0) + (lane & 7);  // + np*16
    const int bcb = (lane >> 3) & 1;                             // + 2*ks

#pragma unroll 1
    for (int c = 0; c < NC; ++c) {
        if (c + 1 < NC) { issue(c + 1); cp_wait<1>(); }
        else { cp_wait<0>(); }
        __syncthreads();

        const uint32_t base = sb0 + (c & (NSTG - 1)) * STAGE;
#pragma unroll
        for (int ks = 0; ks < 4; ++ks) {
            // B frags first (shared across all mt)
            uint32_t bh[4][2], bl[4][2];
#pragma unroll
            for (int np = 0; np < 2; ++np) {
                const uint32_t off = swzoff(brow0 + np * 16, bcb + 2 * ks);
                uint32_t r[4];
                ldsm4(base + OFF_BH + off, r);
                bh[np * 2][0] = r[0]; bh[np * 2][1] = r[1];
                bh[np * 2 + 1][0] = r[2]; bh[np * 2 + 1][1] = r[3];
                ldsm4(base + OFF_BL + off, r);
                bl[np * 2][0] = r[0]; bl[np * 2][1] = r[1];
                bl[np * 2 + 1][0] = r[2]; bl[np * 2 + 1][1] = r[3];
            }
#pragma unroll
            for (int mt = 0; mt < 4; ++mt) {
                const uint32_t off = swzoff(arow0 + mt * 16, acb + 2 * ks);
                uint32_t avh[4], avl[4], ad[4];
                ldsm4(base + off, avh);
                ldsm4(base + ATB + off, avl);
                if (TG) ldsm4(base + 2 * ATB + off, ad);
#pragma unroll
                for (int nt = 0; nt < 4; ++nt) {
                    mma_bf16(accV[mt][nt], avh, bh[nt]);
                    mma_bf16(accV[mt][nt], avl, bh[nt]);
                    mma_bf16(accV[mt][nt], avh, bl[nt]);
                    if (TG) mma_bf16(accD[mt][nt], ad, bh[nt]);
                }
            }
        }
        __syncthreads();
    }

    // ---- Epilogue ----
    const int q2 = 2 * (lane & 3);
#pragma unroll
    for (int mt = 0; mt < 4; ++mt) {
#pragma unroll
        for (int nt = 0; nt < 4; ++nt) {
            const int col = n0 + wn + nt * 8 + q2;
            const float2 bv = *(const float2*)&bias[col];
#pragma unroll
            for (int cp = 0; cp < 2; ++cp) {
                const int row = row0 + wm + mt * 16 + (lane >> 2) + cp * 8;
                const float a0 = accV[mt][nt][cp * 2 + 0];
                const float a1 = accV[mt][nt][cp * 2 + 1];

                if (MODE == 0) {
                    const float2 wv = *(const float2*)&p0[col];
                    const float tv = p1[row];
                    const float pre0 = a0 + tv * wv.x + bv.x;
                    const float pre1 = a1 + tv * wv.y + bv.y;
                    bf16 h0h, h0l, h1h, h1l;
                    split_bf(fmaxf(pre0, 0.f), h0h, h0l);
                    split_bf(fmaxf(pre1, 0.f), h1h, h1l);
                    const bf16 d0 = __float2bfloat16_rn(pre0 > 0.f ? wv.x : 0.f);
                    const bf16 d1 = __float2bfloat16_rn(pre1 > 0.f ? wv.y : 0.f);
                    const size_t o = (size_t)row * HID + col;
                    *(uint32_t*)&ohh[o] = pack2(h0h, h1h);
                    *(uint32_t*)&ohl[o] = pack2(h0l, h1l);
                    *(uint32_t*)&od[o]  = pack2(d0, d1);
                } else if (MODE == 1) {
                    const float pre0 = a0 + bv.x;
                    const float pre1 = a1 + bv.y;
                    bf16 h0h, h0l, h1h, h1l;
                    split_bf(fmaxf(pre0, 0.f), h0h, h0l);
                    split_bf(fmaxf(pre1, 0.f), h1h, h1l);
                    const bf16 d0 = __float2bfloat16_rn(pre0 > 0.f ? accD[mt][nt][cp * 2 + 0] : 0.f);
                    const bf16 d1 = __float2bfloat16_rn(pre1 > 0.f ? accD[mt][nt][cp * 2 + 1] : 0.f);
                    const size_t o = (size_t)row * HID + col;
                    *(uint32_t*)&ohh[o] = pack2(h0h, h1h);
                    *(uint32_t*)&ohl[o] = pack2(h0l, h1l);
                    *(uint32_t*)&od[o]  = pack2(d0, d1);
                } else {
                    const float fnn0 = a0 + bv.x;
                    const float fnn1 = a1 + bv.y;
                    const float dt0 = accD[mt][nt][cp * 2 + 0];
                    const float dt1 = accD[mt][nt][cp * 2 + 1];
                    const float tv = p2[row];
                    const float tc = tv * (1.f - tv);
                    const float om2t = 1.f - 2.f * tv;
                    const size_t xo = (size_t)row * SDIM + col;
                    const float2 x0v = *(const float2*)&p0[xo];
                    const float2 x1v = *(const float2*)&p1[xo];
                    float2 xt, dxt;
                    xt.x = (1.f - tv) * x0v.x + tv * x1v.x + tc * fnn0;
                    xt.y = (1.f - tv) * x0v.y + tv * x1v.y + tc * fnn1;
                    dxt.x = x1v.x - x0v.x + om2t * fnn0 + tc * dt0;
                    dxt.y = x1v.y - x0v.y + om2t * fnn1 + tc * dt1;
                    *(float2*)&out[xo] = xt;
                    *(float2*)&out[(size_t)BATCH * SDIM + xo] = dxt;
                }
            }
        }
    }
}

// ---------------------------------------------------------------------------
// Launch
// ---------------------------------------------------------------------------
extern "C" void kernel_launch(void* const* d_in, const int* in_sizes, int n_in,
                              void* d_out, int out_size) {
    (void)in_sizes; (void)n_in; (void)out_size;
    const float* x0 = (const float*)d_in[0];
    const float* x1 = (const float*)d_in[1];
    const float* t  = (const float*)d_in[2];
    const float* W1 = (const float*)d_in[3];
    const float* b1 = (const float*)d_in[4];
    const float* W2 = (const float*)d_in[5];
    const float* b2 = (const float*)d_in[6];
    const float* W3 = (const float*)d_in[7];
    const float* b3 = (const float*)d_in[8];
    const float* W4 = (const float*)d_in[9];
    const float* b4 = (const float*)d_in[10];
    float* out = (float*)d_out;

    bf16 *zH, *zL, *hAH, *hAL, *hBH, *hBL, *dA, *dB;
    bf16 *w1H, *w1L, *w2H, *w2L, *w3H, *w3L, *w4H, *w4L;
    cudaGetSymbolAddress((void**)&zH, g_z_hi);   cudaGetSymbolAddress((void**)&zL, g_z_lo);
    cudaGetSymbolAddress((void**)&hAH, g_hA_hi); cudaGetSymbolAddress((void**)&hAL, g_hA_lo);
    cudaGetSymbolAddress((void**)&hBH, g_hB_hi); cudaGetSymbolAddress((void**)&hBL, g_hB_lo);
    cudaGetSymbolAddress((void**)&dA, g_dA);     cudaGetSymbolAddress((void**)&dB, g_dB);
    cudaGetSymbolAddress((void**)&w1H, g_wt1_hi); cudaGetSymbolAddress((void**)&w1L, g_wt1_lo);
    cudaGetSymbolAddress((void**)&w2H, g_wt2_hi); cudaGetSymbolAddress((void**)&w2L, g_wt2_lo);
    cudaGetSymbolAddress((void**)&w3H, g_wt3_hi); cudaGetSymbolAddress((void**)&w3L, g_wt3_lo);
    cudaGetSymbolAddress((void**)&w4H, g_wt4_hi); cudaGetSymbolAddress((void**)&w4L, g_wt4_lo);

    constexpr int SM_L1  = NSTG * (2 * ATB + 2 * BTB);   // 2 * 64KB = 131072
    constexpr int SM_MID = NSTG * (3 * ATB + 2 * BTB);   // 2 * 80KB = 163840

    cudaFuncSetAttribute(gemm3_kernel<0, 8, false, 512, 512>,
                         cudaFuncAttributeMaxDynamicSharedMemorySize, SM_L1);
    cudaFuncSetAttribute(gemm3_kernel<1, 16, true, 1024, 1024>,
                         cudaFuncAttributeMaxDynamicSharedMemorySize, SM_MID);
    cudaFuncSetAttribute(gemm3_kernel<2, 16, true, 1024, 1024>,
                         cudaFuncAttributeMaxDynamicSharedMemorySize, SM_MID);

    split_z_kernel<<<(BATCH * SDIM + 255) / 256, 256>>>(x0, x1);
    split_w_kernel<<<(512 * HID + 255) / 256, 256>>>(W1, w1H, w1L, 512, HID);
    split_w_kernel<<<(HID * HID + 255) / 256, 256>>>(W2, w2H, w2L, HID, HID);
    split_w_kernel<<<(HID * HID + 255) / 256, 256>>>(W3, w3H, w3L, HID, HID);
    split_w_kernel<<<(HID * SDIM + 255) / 256, 256>>>(W4, w4H, w4L, HID, SDIM);

    dim3 blk(NT);
    dim3 grid_hid(HID / BN, BATCH / BM);   // (8, 512)
    dim3 grid_out(SDIM / BN, BATCH / BM);  // (2, 512)

    // layer 1: value GEMM over z (K=512); tangent analytic in epilogue
    gemm3_kernel<0, 8, false, 512, 512><<<grid_hid, blk, SM_L1>>>(
        zH, zL, nullptr, w1H, w1L, b1,
        W1 + (size_t)512 * HID, t, nullptr,
        hAH, hAL, dA, nullptr);

    // layer 2: A -> B
    gemm3_kernel<1, 16, true, 1024, 1024><<<grid_hid, blk, SM_MID>>>(
        hAH, hAL, dA, w2H, w2L, b2,
        nullptr, nullptr, nullptr,
        hBH, hBL, dB, nullptr);

    // layer 3: B -> A
    gemm3_kernel<1, 16, true, 1024, 1024><<<grid_hid, blk, SM_MID>>>(
        hBH, hBL, dB, w3H, w3L, b3,
        nullptr, nullptr, nullptr,
        hAH, hAL, dA, nullptr);

    // layer 4 + interpolant combine
    gemm3_kernel<2, 16, true, 1024, 1024><<<grid_out, blk, SM_MID>>>(
        hAH, hAL, dA, w4H, w4L, b4,
        x0, x1, t,
        nullptr, nullptr, nullptr, out);
}